// round 7
// baseline (speedup 1.0000x reference)
#include <cuda_runtime.h>
#include <cstdint>

#define THRESH 0.3f
#define MARGIN 0.1f
#define WEIGHT 0.1f

constexpr int NBLOCKS    = 1024;
constexpr int NCONSUMERS = 256;            // 8 consumer warps
constexpr int NTHREADS   = NCONSUMERS + 32; // + 1 producer warp
constexpr int STAGE_ROWS = 512;
constexpr int NSTAGES    = 8;

constexpr int PRED_TILE_B = STAGE_ROWS * 16;   // 8192
constexpr int TIME_TILE_B = STAGE_ROWS * 4;    // 2048
constexpr int MBAR_FULL  = 0;                  // 8 x 8B
constexpr int MBAR_EMPTY = 64;                 // 8 x 8B
constexpr int PRED_OFF   = 128;
constexpr int TIME_OFF   = PRED_OFF + NSTAGES * PRED_TILE_B;   // 128 + 65536
constexpr int SMEM_BYTES = TIME_OFF + NSTAGES * TIME_TILE_B;   // 82048

// Scratch for deterministic fused reduction (no device allocation allowed).
__device__ float        g_psum[NBLOCKS];
__device__ unsigned int g_pcnt[NBLOCKS];
__device__ unsigned int g_ticket;   // zero-init; last block resets after use

__device__ __forceinline__ uint32_t smem_u32(const void* p) {
    uint32_t a;
    asm("{ .reg .u64 t; cvta.to.shared.u64 t, %1; cvt.u32.u64 %0, t; }"
        : "=r"(a) : "l"(p));
    return a;
}
__device__ __forceinline__ void mbar_init(uint32_t mb, uint32_t count) {
    asm volatile("mbarrier.init.shared.b64 [%0], %1;" :: "r"(mb), "r"(count) : "memory");
}
__device__ __forceinline__ void mbar_expect_tx(uint32_t mb, uint32_t bytes) {
    asm volatile("mbarrier.arrive.expect_tx.shared.b64 _, [%0], %1;"
                 :: "r"(mb), "r"(bytes) : "memory");
}
__device__ __forceinline__ void mbar_arrive(uint32_t mb) {
    asm volatile("mbarrier.arrive.shared.b64 _, [%0];" :: "r"(mb) : "memory");
}
__device__ __forceinline__ void bulk_g2s(uint32_t dst, const void* src,
                                         uint32_t bytes, uint32_t mb) {
    asm volatile(
        "cp.async.bulk.shared::cluster.global.mbarrier::complete_tx::bytes "
        "[%0], [%1], %2, [%3];"
        :: "r"(dst), "l"(src), "r"(bytes), "r"(mb) : "memory");
}
__device__ __forceinline__ void mbar_wait(uint32_t mb, uint32_t parity) {
    asm volatile(
        "{\n\t"
        ".reg .pred P;\n\t"
        "W_%=:\n\t"
        "mbarrier.try_wait.parity.acquire.cta.shared::cta.b64 P, [%0], %1, 0x989680;\n\t"
        "@P bra.uni D_%=;\n\t"
        "bra.uni W_%=;\n\t"
        "D_%=:\n\t"
        "}"
        :: "r"(mb), "r"(parity) : "memory");
}
__device__ __forceinline__ void fence_proxy_async_cta() {
    asm volatile("fence.proxy.async.shared::cta;" ::: "memory");
}

__device__ __forceinline__ void row_accum(float4 p, float t,
                                          float& sum, unsigned int& cnt)
{
    float p4 = p.y, p5 = p.z, p6 = p.w;

    bool a = p4 > THRESH;
    bool b = p5 > THRESH;
    bool c = p6 > THRESH;
    bool m45  = a && b;
    bool m56  = b && c;
    bool m456 = m45 && c;

    // exactly as reference: relu(MARGIN - (p5*t - p4*t)) etc.
    float term45 = fmaxf(MARGIN - (p5 * t - p4 * t), 0.0f);
    float term56 = fmaxf(MARGIN - (p6 * t - p5 * t), 0.0f);
    float d45 = fabsf(p5 - p4);
    float d56 = fabsf(p6 - p5);
    float termO = fmaxf(d45 - d56 + MARGIN, 0.0f);

    sum += m45  ? term45 : 0.0f;
    sum += m56  ? term56 : 0.0f;
    sum += m456 ? termO  : 0.0f;
    cnt += (unsigned)m45 + (unsigned)m56 + (unsigned)m456;
}

__global__ __launch_bounds__(NTHREADS)
void tcl_ws(const float4* __restrict__ pred,   // (B,4) f32 rows
            const float*  __restrict__ times,  // (B,)
            float* __restrict__ out,
            int B, int chunk)                  // chunk % STAGE_ROWS == 0
{
    extern __shared__ char smem[];
    const uint32_t sb = smem_u32(smem);

    const int tid  = threadIdx.x;
    const int lane = tid & 31;
    const int wid  = tid >> 5;

    const int row_base = blockIdx.x * chunk;
    int rows_cta = B - row_base;
    if (rows_cta < 0) rows_cta = 0;
    if (rows_cta > chunk) rows_cta = chunk;
    const int full_tiles = rows_cta / STAGE_ROWS;

    if (tid == 0) {
        #pragma unroll
        for (int j = 0; j < NSTAGES; j++) {
            mbar_init(sb + MBAR_FULL  + j * 8, 1);   // expect_tx arrival
            mbar_init(sb + MBAR_EMPTY + j * 8, 8);   // 8 consumer warps
        }
        fence_proxy_async_cta();
    }
    __syncthreads();

    float        sum = 0.0f;
    unsigned int cnt = 0;

    if (wid == 8) {
        // ---- Producer warp: free-running bulk-copy issue with backpressure ----
        if (lane == 0) {
            for (int s = 0; s < full_tiles; s++) {
                uint32_t buf  = (uint32_t)s & (NSTAGES - 1);
                uint32_t wrap = (uint32_t)s >> 3;
                mbar_wait(sb + MBAR_EMPTY + buf * 8, (wrap & 1u) ^ 1u);
                uint32_t fmb = sb + MBAR_FULL + buf * 8;
                size_t r0 = (size_t)row_base + (size_t)s * STAGE_ROWS;
                mbar_expect_tx(fmb, PRED_TILE_B + TIME_TILE_B);
                bulk_g2s(sb + PRED_OFF + buf * PRED_TILE_B,
                         (const char*)pred + r0 * 16, PRED_TILE_B, fmb);
                bulk_g2s(sb + TIME_OFF + buf * TIME_TILE_B,
                         (const char*)times + r0 * 4, TIME_TILE_B, fmb);
            }
        }
    } else {
        // ---- 8 consumer warps ----
        for (int s = 0; s < full_tiles; s++) {
            uint32_t buf  = (uint32_t)s & (NSTAGES - 1);
            uint32_t wrap = (uint32_t)s >> 3;
            mbar_wait(sb + MBAR_FULL + buf * 8, wrap & 1u);

            const float4* pt = (const float4*)(smem + PRED_OFF + buf * PRED_TILE_B);
            const float*  tt = (const float*)(smem + TIME_OFF + buf * TIME_TILE_B);
            #pragma unroll
            for (int k = 0; k < STAGE_ROWS / NCONSUMERS; k++) {
                int r = tid + k * NCONSUMERS;
                row_accum(pt[r], tt[r], sum, cnt);
            }
            __syncwarp();
            if (lane == 0) mbar_arrive(sb + MBAR_EMPTY + buf * 8);
        }
    }

    // Generic tail (empty for the bench shape).
    for (int r = row_base + full_tiles * STAGE_ROWS + tid;
         r < row_base + rows_cta; r += NTHREADS) {
        row_accum(pred[r], times[r], sum, cnt);
    }

    // Block reduction over all 9 warps (producer contributes zeros).
    #pragma unroll
    for (int off = 16; off > 0; off >>= 1) {
        sum += __shfl_down_sync(0xFFFFFFFFu, sum, off);
        cnt += __shfl_down_sync(0xFFFFFFFFu, cnt, off);
    }

    __shared__ float        s_sum[16];
    __shared__ unsigned int s_cnt[16];
    __shared__ bool         s_last;
    if (lane == 0) { s_sum[wid] = sum; s_cnt[wid] = cnt; }
    __syncthreads();

    if (wid == 0) {
        sum = (lane < NTHREADS / 32) ? s_sum[lane] : 0.0f;
        cnt = (lane < NTHREADS / 32) ? s_cnt[lane] : 0u;
        #pragma unroll
        for (int off = 8; off > 0; off >>= 1) {
            sum += __shfl_down_sync(0xFFFFFFFFu, sum, off);
            cnt += __shfl_down_sync(0xFFFFFFFFu, cnt, off);
        }
        if (lane == 0) {
            g_psum[blockIdx.x] = sum;
            g_pcnt[blockIdx.x] = cnt;
            __threadfence();
            unsigned int ticket = atomicAdd(&g_ticket, 1u);
            s_last = (ticket == (unsigned)gridDim.x - 1u);
        }
    }
    __syncthreads();

    if (s_last) {
        float        fsum = 0.0f;
        unsigned int fcnt = 0;
        for (int k = tid; k < NBLOCKS; k += NTHREADS) {
            fsum += g_psum[k];
            fcnt += g_pcnt[k];
        }
        #pragma unroll
        for (int off = 16; off > 0; off >>= 1) {
            fsum += __shfl_down_sync(0xFFFFFFFFu, fsum, off);
            fcnt += __shfl_down_sync(0xFFFFFFFFu, fcnt, off);
        }
        if (lane == 0) { s_sum[wid] = fsum; s_cnt[wid] = fcnt; }
        __syncthreads();
        if (wid == 0) {
            fsum = (lane < NTHREADS / 32) ? s_sum[lane] : 0.0f;
            fcnt = (lane < NTHREADS / 32) ? s_cnt[lane] : 0u;
            #pragma unroll
            for (int off = 8; off > 0; off >>= 1) {
                fsum += __shfl_down_sync(0xFFFFFFFFu, fsum, off);
                fcnt += __shfl_down_sync(0xFFFFFFFFu, fcnt, off);
            }
            if (lane == 0) {
                float count = (float)fcnt;
                float loss  = (count > 0.0f) ? (fsum / fmaxf(count, 1.0f)) : fsum;
                out[0] = WEIGHT * loss;
                g_ticket = 0u;   // reset for next graph replay
            }
        }
    }
}

extern "C" void kernel_launch(void* const* d_in, const int* in_sizes, int n_in,
                              void* d_out, int out_size)
{
    const float4* pred  = (const float4*)d_in[0];  // (B,4) float32
    const float*  times = (const float*)d_in[1];   // (B,1) float32
    float*        out   = (float*)d_out;

    int B = in_sizes[1];

    int chunk = (B + NBLOCKS - 1) / NBLOCKS;
    chunk = ((chunk + STAGE_ROWS - 1) / STAGE_ROWS) * STAGE_ROWS;  // 8192 for B=2^23

    cudaFuncSetAttribute(tcl_ws,
                         cudaFuncAttributeMaxDynamicSharedMemorySize,
                         SMEM_BYTES);

    tcl_ws<<<NBLOCKS, NTHREADS, SMEM_BYTES>>>(pred, times, out, B, chunk);
}

// round 8
// speedup vs baseline: 1.2510x; 1.2510x over previous
#include <cuda_runtime.h>

#define THRESH 0.3f
#define MARGIN 0.1f
#define WEIGHT 0.1f

constexpr int NBLOCKS  = 592;    // 148 SMs x 4 CTAs, guaranteed single wave
constexpr int NTHREADS = 256;    // 8 warps
constexpr int TILE     = 128;    // rows per warp-tile

// Scratch for deterministic fused reduction (no device allocation allowed).
__device__ float        g_psum[NBLOCKS];
__device__ unsigned int g_pcnt[NBLOCKS];
__device__ unsigned int g_ticket;   // zero-init; last block resets after use

__device__ __forceinline__ void row_accum(float4 p, float t,
                                          float& sum, unsigned int& cnt)
{
    float p4 = p.y, p5 = p.z, p6 = p.w;

    bool a = p4 > THRESH;
    bool b = p5 > THRESH;
    bool c = p6 > THRESH;
    bool m45  = a && b;
    bool m56  = b && c;
    bool m456 = m45 && c;

    // exactly as reference: relu(MARGIN - (p5*t - p4*t)) etc.
    float term45 = fmaxf(MARGIN - (p5 * t - p4 * t), 0.0f);
    float term56 = fmaxf(MARGIN - (p6 * t - p5 * t), 0.0f);
    float d45 = fabsf(p5 - p4);
    float d56 = fabsf(p6 - p5);
    float termO = fmaxf(d45 - d56 + MARGIN, 0.0f);

    sum += m45  ? term45 : 0.0f;
    sum += m56  ? term56 : 0.0f;
    sum += m456 ? termO  : 0.0f;
    cnt += (unsigned)m45 + (unsigned)m56 + (unsigned)m456;
}

__global__ __launch_bounds__(NTHREADS, 4)
void tcl_wtile(const float4* __restrict__ pred,   // (B,4) f32 rows
               const float*  __restrict__ times,  // (B,)
               float* __restrict__ out,
               int B)
{
    // Double-buffered per-warp staging for times (8 warps x 128 floats x 2)
    __shared__ float tbuf[2][NTHREADS / 32][TILE];

    const int tid  = threadIdx.x;
    const int lane = tid & 31;
    const int wid  = tid >> 5;

    const int warps_total = NBLOCKS * (NTHREADS / 32);
    const int wgid        = blockIdx.x * (NTHREADS / 32) + wid;
    const int ntiles      = B / TILE;

    float        sum0 = 0.0f, sum1 = 0.0f;
    unsigned int cnt0 = 0,    cnt1 = 0;

    int dbuf = 0;
    for (int tile = wgid; tile < ntiles; tile += warps_total, dbuf ^= 1) {
        const int base = tile * TILE;

        // 5 wide, fully-coalesced LDG.128s issued back-to-back:
        float4 tv = __ldcs((const float4*)(times + base) + lane); // rows base+4*lane..+3
        float4 p0 = __ldcs(&pred[base + lane]);
        float4 p1 = __ldcs(&pred[base + 32 + lane]);
        float4 p2 = __ldcs(&pred[base + 64 + lane]);
        float4 p3 = __ldcs(&pred[base + 96 + lane]);

        // Stage times through SMEM to realign t[row] with pred row ownership.
        *(float4*)&tbuf[dbuf][wid][4 * lane] = tv;
        __syncwarp();
        float t0 = tbuf[dbuf][wid][lane];
        float t1 = tbuf[dbuf][wid][32 + lane];
        float t2 = tbuf[dbuf][wid][64 + lane];
        float t3 = tbuf[dbuf][wid][96 + lane];

        row_accum(p0, t0, sum0, cnt0);
        row_accum(p1, t1, sum1, cnt1);
        row_accum(p2, t2, sum0, cnt0);
        row_accum(p3, t3, sum1, cnt1);
    }

    // Tail rows (B % TILE) — empty for the bench shape, kept for generality.
    {
        const int gtid = blockIdx.x * NTHREADS + tid;
        for (int r = ntiles * TILE + gtid; r < B; r += NBLOCKS * NTHREADS) {
            row_accum(pred[r], times[r], sum0, cnt0);
        }
    }

    float        sum = sum0 + sum1;
    unsigned int cnt = cnt0 + cnt1;

    // Block reduction
    #pragma unroll
    for (int off = 16; off > 0; off >>= 1) {
        sum += __shfl_down_sync(0xFFFFFFFFu, sum, off);
        cnt += __shfl_down_sync(0xFFFFFFFFu, cnt, off);
    }

    __shared__ float        s_sum[NTHREADS / 32];
    __shared__ unsigned int s_cnt[NTHREADS / 32];
    __shared__ bool         s_last;
    if (lane == 0) { s_sum[wid] = sum; s_cnt[wid] = cnt; }
    __syncthreads();

    if (wid == 0) {
        sum = (lane < NTHREADS / 32) ? s_sum[lane] : 0.0f;
        cnt = (lane < NTHREADS / 32) ? s_cnt[lane] : 0u;
        #pragma unroll
        for (int off = 4; off > 0; off >>= 1) {
            sum += __shfl_down_sync(0xFFFFFFFFu, sum, off);
            cnt += __shfl_down_sync(0xFFFFFFFFu, cnt, off);
        }
        if (lane == 0) {
            g_psum[blockIdx.x] = sum;
            g_pcnt[blockIdx.x] = cnt;
            __threadfence();
            unsigned int ticket = atomicAdd(&g_ticket, 1u);
            s_last = (ticket == (unsigned)gridDim.x - 1u);
        }
    }
    __syncthreads();

    // Last block reduces all partials (values deterministic regardless of order).
    if (s_last) {
        float        fsum = 0.0f;
        unsigned int fcnt = 0;
        for (int k = tid; k < NBLOCKS; k += NTHREADS) {
            fsum += g_psum[k];
            fcnt += g_pcnt[k];
        }
        #pragma unroll
        for (int off = 16; off > 0; off >>= 1) {
            fsum += __shfl_down_sync(0xFFFFFFFFu, fsum, off);
            fcnt += __shfl_down_sync(0xFFFFFFFFu, fcnt, off);
        }
        if (lane == 0) { s_sum[wid] = fsum; s_cnt[wid] = fcnt; }
        __syncthreads();
        if (wid == 0) {
            fsum = (lane < NTHREADS / 32) ? s_sum[lane] : 0.0f;
            fcnt = (lane < NTHREADS / 32) ? s_cnt[lane] : 0u;
            #pragma unroll
            for (int off = 4; off > 0; off >>= 1) {
                fsum += __shfl_down_sync(0xFFFFFFFFu, fsum, off);
                fcnt += __shfl_down_sync(0xFFFFFFFFu, fcnt, off);
            }
            if (lane == 0) {
                float count = (float)fcnt;
                float loss  = (count > 0.0f) ? (fsum / fmaxf(count, 1.0f)) : fsum;
                out[0] = WEIGHT * loss;
                g_ticket = 0u;   // reset for next graph replay
            }
        }
    }
}

extern "C" void kernel_launch(void* const* d_in, const int* in_sizes, int n_in,
                              void* d_out, int out_size)
{
    const float4* pred  = (const float4*)d_in[0];  // (B,4) float32
    const float*  times = (const float*)d_in[1];   // (B,1) float32
    float*        out   = (float*)d_out;

    int B = in_sizes[1];   // element count of relative_times = B

    tcl_wtile<<<NBLOCKS, NTHREADS>>>(pred, times, out, B);
}